// round 13
// baseline (speedup 1.0000x reference)
#include <cuda_runtime.h>
#include <cuda_fp16.h>
#include <math.h>
#include <stdint.h>

#define N_NODES 50000
#define N_EDGES 800000
#define N_CLUST 5000
#define GRID_SMS 152
#define NBLK_N 49   // ceil(50000/1024)
#define NBLK_C 5    // ceil(5000/1024)

// ---------------- static device scratch ----------------
__device__ __align__(16) float g_x1[N_NODES * 128];
__device__ __align__(16) float g_x2[N_NODES * 256];
__device__ __align__(16) float g_x3[N_NODES * 512];   // only h3 half (first 256) is written/used
__device__ __align__(16) __half g_h1[N_NODES * 64];    // fp16 copy of h (layer0)
__device__ __align__(16) __half g_h2[N_NODES * 128];   // layer1
__device__ __align__(16) __half g_h3[N_NODES * 256];   // layer2
__device__ __align__(16) float g_pooled[N_CLUST * 512];
__device__ __align__(16) float g_partial[64 * 512];
__device__ __align__(16) float g_norms[512];

__device__ int g_deg[N_NODES];
__device__ int g_rowptr[N_NODES + 1];
__device__ int g_cursor[N_NODES];
__device__ int g_esrc[N_EDGES];
__device__ int g_cdeg[N_CLUST];
__device__ int g_crow[N_CLUST + 1];
__device__ int g_ccur[N_CLUST];
__device__ int g_cnodes[N_NODES];
__device__ int g_bsumN[NBLK_N];
__device__ int g_bsumC[NBLK_C];
__device__ int g_task[3];          // work-stealing counters (one per MLP layer)

__device__ __forceinline__ float4 fmax4(float4 a, float4 b) {
    return make_float4(fmaxf(a.x, b.x), fmaxf(a.y, b.y), fmaxf(a.z, b.z), fmaxf(a.w, b.w));
}
__device__ __forceinline__ unsigned h2u(__half2 h) {
    return *reinterpret_cast<unsigned*>(&h);
}

// ---------------- CSR build ----------------
__global__ void zero_counts_k() {
    int i = blockIdx.x * blockDim.x + threadIdx.x;
    if (i < N_NODES) g_deg[i] = 0;
    if (i < N_CLUST) g_cdeg[i] = 0;
    if (i < 3) g_task[i] = 0;
}

__global__ void hist_k(const int* __restrict__ dst, const int* __restrict__ clu) {
    int i = blockIdx.x * blockDim.x + threadIdx.x;
    if (i < N_EDGES) atomicAdd(&g_deg[dst[i]], 1);
    if (i < N_NODES) atomicAdd(&g_cdeg[clu[i]], 1);
}

// phase 1: per-1024-chunk sums. grid = NBLK_N + NBLK_C, 256 threads
__global__ void scan_p1_k() {
    int blk = blockIdx.x, t = threadIdx.x;
    const int* in; int n, lb;
    if (blk < NBLK_N) { in = g_deg;  n = N_NODES; lb = blk; }
    else              { in = g_cdeg; n = N_CLUST; lb = blk - NBLK_N; }
    int i0 = lb * 1024 + t * 4;
    int s = 0;
#pragma unroll
    for (int u = 0; u < 4; u++) if (i0 + u < n) s += in[i0 + u];
    int lane = t & 31, w = t >> 5;
#pragma unroll
    for (int o = 16; o > 0; o >>= 1) s += __shfl_down_sync(0xffffffffu, s, o);
    __shared__ int wt[8];
    if (lane == 0) wt[w] = s;
    __syncthreads();
    if (t == 0) {
        int tot = 0;
#pragma unroll
        for (int i = 0; i < 8; i++) tot += wt[i];
        if (blk < NBLK_N) g_bsumN[lb] = tot; else g_bsumC[lb] = tot;
    }
}

// phase 3 (p2 fused): block computes its own base, does local scan, writes
// rowptr AND cursor; the thread holding the final element writes out[n].
__global__ void scan_p3_k() {
    int blk = blockIdx.x, t = threadIdx.x;
    const int* in; int* outp; int* cur; const int* bs; int n, lb;
    if (blk < NBLK_N) { in = g_deg;  outp = g_rowptr; cur = g_cursor; bs = g_bsumN; n = N_NODES; lb = blk; }
    else              { in = g_cdeg; outp = g_crow;   cur = g_ccur;   bs = g_bsumC; n = N_CLUST; lb = blk - NBLK_N; }
    __shared__ int sbase;
    if (t == 0) {
        int s = 0;
        for (int i = 0; i < lb; i++) s += bs[i];
        sbase = s;
    }
    int i0 = lb * 1024 + t * 4;
    int v[4];
#pragma unroll
    for (int u = 0; u < 4; u++) v[u] = (i0 + u < n) ? in[i0 + u] : 0;
    int ts = v[0] + v[1] + v[2] + v[3];
    int lane = t & 31, w = t >> 5;
    int s = ts;
#pragma unroll
    for (int o = 1; o < 32; o <<= 1) {
        int x = __shfl_up_sync(0xffffffffu, s, o);
        if (lane >= o) s += x;
    }
    __shared__ int wt[8], wte[8];
    if (lane == 31) wt[w] = s;
    __syncthreads();
    if (t < 8) { int e = 0; for (int i = 0; i < t; i++) e += wt[i]; wte[t] = e; }
    __syncthreads();
    int run = s - ts + wte[w] + sbase;
#pragma unroll
    for (int u = 0; u < 4; u++) {
        if (i0 + u < n) {
            outp[i0 + u] = run; cur[i0 + u] = run;
            run += v[u];
            if (i0 + u == n - 1) outp[n] = run;
        }
    }
}

__global__ void fill_k(const int* __restrict__ src, const int* __restrict__ dst,
                       const int* __restrict__ clu) {
    int i = blockIdx.x * blockDim.x + threadIdx.x;
    if (i < N_EDGES) {
        int slot = atomicAdd(&g_cursor[dst[i]], 1);
        g_esrc[slot] = src[i];
    }
    if (i < N_NODES) {
        int slot = atomicAdd(&g_ccur[clu[i]], 1);
        g_cnodes[slot] = i;
    }
}

// ---------------- per-node MLP: Linear(CIN->64) -> LN -> ReLU -> Linear(64->CIN) ----------------
// Work-stealing task loop (atomic counter) removes the static-schedule tail.
// Epilogue also writes an fp16 copy of h for the AGG/pool gathers.
template <int CIN, int NW, int NB>
__global__ void __launch_bounds__(NW * 32, 1) mlp_k(
    const float* __restrict__ xin_ext,
    const float* __restrict__ w1, const float* __restrict__ b1,
    const float* __restrict__ gg, const float* __restrict__ be,
    const float* __restrict__ w2, const float* __restrict__ b2)
{
    constexpr int CPL = CIN / 32;
    constexpr int LIDX = (CIN == 64) ? 0 : (CIN == 128) ? 1 : 2;
    const float* xin;
    float* xout;
    __half* hbuf;
    if constexpr (CIN == 64)       { xin = xin_ext; xout = g_x1; hbuf = g_h1; }
    else if constexpr (CIN == 128) { xin = g_x1;    xout = g_x2; hbuf = g_h2; }
    else                           { xin = g_x2;    xout = g_x3; hbuf = g_h3; }

    extern __shared__ float smem[];
    float* w1s = smem;             // [CIN][64]
    float* w2s = smem + CIN * 64;  // [64][CIN]
    int tid = threadIdx.x;
    int L = tid & 31;
    int w = tid >> 5;
    float* xs = smem + CIN * 128 + w * (NB * CIN);

    for (int i = tid; i < CIN * 64; i += NW * 32) { w1s[i] = w1[i]; w2s[i] = w2[i]; }
    __syncthreads();

    float b1a = b1[2 * L], b1b = b1[2 * L + 1];
    float ga = gg[2 * L], gb = gg[2 * L + 1];
    float bea = be[2 * L], beb = be[2 * L + 1];
    float b2r[CPL];
#pragma unroll
    for (int k = 0; k < CPL; k++) b2r[k] = b2[CPL * L + k];

    const int ntasks = (N_NODES + NB - 1) / NB;
    while (true) {
        int task;
        if (L == 0) task = atomicAdd(&g_task[LIDX], 1);
        task = __shfl_sync(0xffffffffu, task, 0);
        if (task >= ntasks) break;
        int n0 = task * NB;
#pragma unroll
        for (int b = 0; b < NB; b++) {
            int n = n0 + b;
            if (n < N_NODES) {
                const float4* xr = reinterpret_cast<const float4*>(xin + (size_t)n * CIN);
                float4* xd = reinterpret_cast<float4*>(xs + b * CIN);
                for (int k = L; k < CIN / 4; k += 32) xd[k] = xr[k];
            }
        }
        __syncwarp();

        // ---- h = x @ w1 + b1 ----
        float a0[NB], a1[NB];
#pragma unroll
        for (int b = 0; b < NB; b++) { a0[b] = b1a; a1[b] = b1b; }
#pragma unroll 2
        for (int c = 0; c < CIN; c += 4) {
            float4 xv[NB];
#pragma unroll
            for (int b = 0; b < NB; b++) xv[b] = *reinterpret_cast<const float4*>(&xs[b * CIN + c]);
#pragma unroll
            for (int u = 0; u < 4; u++) {
                float2 wv = *reinterpret_cast<const float2*>(&w1s[(c + u) * 64 + 2 * L]);
#pragma unroll
                for (int b = 0; b < NB; b++) {
                    float xb = (u == 0) ? xv[b].x : (u == 1) ? xv[b].y : (u == 2) ? xv[b].z : xv[b].w;
                    a0[b] = fmaf(xb, wv.x, a0[b]);
                    a1[b] = fmaf(xb, wv.y, a1[b]);
                }
            }
        }

        // ---- LayerNorm(64) + ReLU ----
        float h0[NB], h1[NB];
#pragma unroll
        for (int b = 0; b < NB; b++) {
            float s = a0[b] + a1[b];
#pragma unroll
            for (int o = 16; o > 0; o >>= 1) s += __shfl_xor_sync(0xffffffffu, s, o);
            float mu = s * (1.0f / 64.0f);
            float e0 = a0[b] - mu, e1 = a1[b] - mu;
            float q = e0 * e0 + e1 * e1;
#pragma unroll
            for (int o = 16; o > 0; o >>= 1) q += __shfl_xor_sync(0xffffffffu, q, o);
            float rs = rsqrtf(q * (1.0f / 64.0f) + 1e-5f);
            h0[b] = fmaxf(fmaf(e0 * rs, ga, bea), 0.0f);
            h1[b] = fmaxf(fmaf(e1 * rs, gb, beb), 0.0f);
        }
        __syncwarp();
#pragma unroll
        for (int b = 0; b < NB; b++)
            *reinterpret_cast<float2*>(&xs[b * CIN + 2 * L]) = make_float2(h0[b], h1[b]);
        __syncwarp();

        // ---- out = h @ w2 + b2 ----
        float acc[NB][CPL];
#pragma unroll
        for (int b = 0; b < NB; b++)
#pragma unroll
            for (int k = 0; k < CPL; k++) acc[b][k] = b2r[k];

#pragma unroll 2
        for (int j = 0; j < 64; j += 4) {
            float4 hv[NB];
#pragma unroll
            for (int b = 0; b < NB; b++) hv[b] = *reinterpret_cast<const float4*>(&xs[b * CIN + j]);
#pragma unroll
            for (int u = 0; u < 4; u++) {
                if constexpr (CPL >= 4) {
#pragma unroll
                    for (int k = 0; k < CPL; k += 4) {
                        float4 wv = *reinterpret_cast<const float4*>(&w2s[(j + u) * CIN + CPL * L + k]);
#pragma unroll
                        for (int b = 0; b < NB; b++) {
                            float hb = (u == 0) ? hv[b].x : (u == 1) ? hv[b].y : (u == 2) ? hv[b].z : hv[b].w;
                            acc[b][k + 0] = fmaf(hb, wv.x, acc[b][k + 0]);
                            acc[b][k + 1] = fmaf(hb, wv.y, acc[b][k + 1]);
                            acc[b][k + 2] = fmaf(hb, wv.z, acc[b][k + 2]);
                            acc[b][k + 3] = fmaf(hb, wv.w, acc[b][k + 3]);
                        }
                    }
                } else {
                    float2 wv = *reinterpret_cast<const float2*>(&w2s[(j + u) * CIN + 2 * L]);
#pragma unroll
                    for (int b = 0; b < NB; b++) {
                        float hb = (u == 0) ? hv[b].x : (u == 1) ? hv[b].y : (u == 2) ? hv[b].z : hv[b].w;
                        acc[b][0] = fmaf(hb, wv.x, acc[b][0]);
                        acc[b][1] = fmaf(hb, wv.y, acc[b][1]);
                    }
                }
            }
        }

#pragma unroll
        for (int b = 0; b < NB; b++) {
            int n = n0 + b;
            if (n < N_NODES) {
                float* orow = xout + (size_t)n * (2 * CIN) + CPL * L;
                __half* hrow = hbuf + (size_t)n * CIN + CPL * L;
                if constexpr (CPL == 2) {
                    *reinterpret_cast<float2*>(orow) = make_float2(acc[b][0], acc[b][1]);
                    *reinterpret_cast<unsigned*>(hrow) =
                        h2u(__floats2half2_rn(acc[b][0], acc[b][1]));
                } else if constexpr (CPL == 4) {
                    *reinterpret_cast<float4*>(orow) =
                        make_float4(acc[b][0], acc[b][1], acc[b][2], acc[b][3]);
                    uint2 hp;
                    hp.x = h2u(__floats2half2_rn(acc[b][0], acc[b][1]));
                    hp.y = h2u(__floats2half2_rn(acc[b][2], acc[b][3]));
                    *reinterpret_cast<uint2*>(hrow) = hp;
                } else {
#pragma unroll
                    for (int k = 0; k < CPL; k += 4)
                        *reinterpret_cast<float4*>(orow + k) =
                            make_float4(acc[b][k], acc[b][k + 1], acc[b][k + 2], acc[b][k + 3]);
                    uint4 hp;
                    hp.x = h2u(__floats2half2_rn(acc[b][0], acc[b][1]));
                    hp.y = h2u(__floats2half2_rn(acc[b][2], acc[b][3]));
                    hp.z = h2u(__floats2half2_rn(acc[b][4], acc[b][5]));
                    hp.w = h2u(__floats2half2_rn(acc[b][6], acc[b][7]));
                    *reinterpret_cast<uint4*>(hrow) = hp;
                }
            }
        }
        __syncwarp();
    }
}

// ---------------- scatter-max via CSR gather (fp16 rows): warp per dst node ----------------
// Used for layers 0 and 1 only (layer-2 agg is fused into pool_fused_k).
template <int CIN>
__global__ void agg_k() {
    constexpr int CPL = CIN / 32;   // halves per lane
    constexpr int H2 = CPL / 2;     // half2 per lane
    const __half* hbuf; float* xout;
    if constexpr (CIN == 64)       { hbuf = g_h1; xout = g_x1; }
    else                           { hbuf = g_h2; xout = g_x2; }

    int gw = (blockIdx.x * blockDim.x + threadIdx.x) >> 5;
    int L = threadIdx.x & 31;
    if (gw >= N_NODES) return;
    int beg = g_rowptr[gw], end = g_rowptr[gw + 1];
    const __half2 NEGH = __half2half2(__ushort_as_half((unsigned short)0xFC00));  // -inf,-inf

    __half2 m[H2];
#pragma unroll
    for (int k = 0; k < H2; k++) m[k] = NEGH;

    int e = beg;
    for (; e + 2 <= end; e += 2) {
        int s0 = g_esrc[e], s1 = g_esrc[e + 1];
        const __half* p0 = hbuf + (size_t)s0 * CIN + CPL * L;
        const __half* p1 = hbuf + (size_t)s1 * CIN + CPL * L;
        if constexpr (H2 == 1) {
            __half2 v0 = *reinterpret_cast<const __half2*>(p0);
            __half2 v1 = *reinterpret_cast<const __half2*>(p1);
            m[0] = __hmax2(m[0], __hmax2(v0, v1));
        } else {
            uint2 r0 = *reinterpret_cast<const uint2*>(p0);
            uint2 r1 = *reinterpret_cast<const uint2*>(p1);
            const __half2* a = reinterpret_cast<const __half2*>(&r0);
            const __half2* b = reinterpret_cast<const __half2*>(&r1);
#pragma unroll
            for (int k = 0; k < 2; k++) m[k] = __hmax2(m[k], __hmax2(a[k], b[k]));
        }
    }
    if (e < end) {
        int s0 = g_esrc[e];
        const __half* p0 = hbuf + (size_t)s0 * CIN + CPL * L;
        if constexpr (H2 == 1) {
            m[0] = __hmax2(m[0], *reinterpret_cast<const __half2*>(p0));
        } else {
            uint2 r0 = *reinterpret_cast<const uint2*>(p0);
            const __half2* a = reinterpret_cast<const __half2*>(&r0);
#pragma unroll
            for (int k = 0; k < 2; k++) m[k] = __hmax2(m[k], a[k]);
        }
    }

    float* orow = xout + (size_t)gw * (2 * CIN) + CIN + CPL * L;
    bool empty = (beg == end);
    if constexpr (H2 == 1) {
        float2 f = empty ? make_float2(0.f, 0.f) : __half22float2(m[0]);
        *reinterpret_cast<float2*>(orow) = f;
    } else {
        float2 f0 = empty ? make_float2(0.f, 0.f) : __half22float2(m[0]);
        float2 f1 = empty ? make_float2(0.f, 0.f) : __half22float2(m[1]);
        *reinterpret_cast<float4*>(orow) = make_float4(f0.x, f0.y, f1.x, f1.y);
    }
}

// ---------------- fused cluster max-pool + layer-2 scatter-max ----------------
// pooled[c] = [ max_{n in c} h3[n]  |  max_{n in c} (agg3[n] or 0 if deg(n)==0) ]
// agg3[n] = max_{e: dst=n} h3[src] computed inline from fp16 g_h3 (identical
// values to the old agg_k<256> path: same fp16 maxes, upconverted once).
__global__ void pool_fused_k() {
    int gw = (blockIdx.x * blockDim.x + threadIdx.x) >> 5;
    int L = threadIdx.x & 31;
    if (gw >= N_CLUST) return;
    int cbeg = g_crow[gw], cend = g_crow[gw + 1];
    const float NEG = __int_as_float(0xff800000);
    const __half2 NEGH = __half2half2(__ushort_as_half((unsigned short)0xFC00));

    float4 hm[2];
    hm[0] = make_float4(NEG, NEG, NEG, NEG);
    hm[1] = make_float4(NEG, NEG, NEG, NEG);
    __half2 am[4];
#pragma unroll
    for (int k = 0; k < 4; k++) am[k] = NEGH;
    bool any_empty_node = false;

    for (int e = cbeg; e < cend; e++) {
        int n = g_cnodes[e];
        // h3 half (fp32 exact, lane owns 8 floats at 8L)
        const float4* hr = reinterpret_cast<const float4*>(g_x3 + (size_t)n * 512 + 8 * L);
        hm[0] = fmax4(hm[0], hr[0]);
        hm[1] = fmax4(hm[1], hr[1]);
        // agg3 gather from fp16 h3 rows (lane owns 8 halves at 8L)
        int rb = g_rowptr[n], re = g_rowptr[n + 1];
        if (rb == re) any_empty_node = true;
        int q = rb;
        for (; q + 2 <= re; q += 2) {
            int s0 = g_esrc[q], s1 = g_esrc[q + 1];
            uint4 r0 = *reinterpret_cast<const uint4*>(g_h3 + (size_t)s0 * 256 + 8 * L);
            uint4 r1 = *reinterpret_cast<const uint4*>(g_h3 + (size_t)s1 * 256 + 8 * L);
            const __half2* a = reinterpret_cast<const __half2*>(&r0);
            const __half2* b = reinterpret_cast<const __half2*>(&r1);
#pragma unroll
            for (int k = 0; k < 4; k++) am[k] = __hmax2(am[k], __hmax2(a[k], b[k]));
        }
        if (q < re) {
            int s0 = g_esrc[q];
            uint4 r0 = *reinterpret_cast<const uint4*>(g_h3 + (size_t)s0 * 256 + 8 * L);
            const __half2* a = reinterpret_cast<const __half2*>(&r0);
#pragma unroll
            for (int k = 0; k < 4; k++) am[k] = __hmax2(am[k], a[k]);
        }
    }

    bool cempty = (cbeg == cend);
    // empty nodes contribute 0 to the cluster agg-max
    if (any_empty_node) {
        const __half2 Z = __half2half2(__ushort_as_half((unsigned short)0));
#pragma unroll
        for (int k = 0; k < 4; k++) am[k] = __hmax2(am[k], Z);
    }

    float* prow = g_pooled + (size_t)gw * 512;
    // h half
    if (cempty) {
        hm[0] = make_float4(0.f, 0.f, 0.f, 0.f);
        hm[1] = make_float4(0.f, 0.f, 0.f, 0.f);
    }
    reinterpret_cast<float4*>(prow + 8 * L)[0] = hm[0];
    reinterpret_cast<float4*>(prow + 8 * L)[1] = hm[1];
    // agg half: pair (am[k], am[k+1]) = 4 floats at float-offset 2k within the
    // lane's 8-float slice (FIXED: was 4*k, which skipped/clobbered memory)
#pragma unroll
    for (int k = 0; k < 4; k += 2) {
        float2 f0 = cempty ? make_float2(0.f, 0.f) : __half22float2(am[k]);
        float2 f1 = cempty ? make_float2(0.f, 0.f) : __half22float2(am[k + 1]);
        *reinterpret_cast<float4*>(prow + 256 + 8 * L + 2 * k) = make_float4(f0.x, f0.y, f1.x, f1.y);
    }
}

// ---------------- column L2 norm + scale ----------------
__global__ void colsum_k() {
    int b = blockIdx.x, c = threadIdx.x;
    int per = (N_CLUST + 63) / 64;
    int r0 = b * per;
    int r1 = r0 + per; if (r1 > N_CLUST) r1 = N_CLUST;
    float s = 0.0f;
    for (int r = r0; r < r1; r++) {
        float v = g_pooled[(size_t)r * 512 + c];
        s = fmaf(v, v, s);
    }
    g_partial[b * 512 + c] = s;
}

__global__ void norm_k() {
    int c = threadIdx.x;
    float s = 0.0f;
    for (int b = 0; b < 64; b++) s += g_partial[b * 512 + c];
    g_norms[c] = sqrtf(s);
}

__global__ void scale_k(float* __restrict__ out) {
    int idx = blockIdx.x * blockDim.x + threadIdx.x;
    if (idx < N_CLUST * 512) out[idx] = g_pooled[idx] / g_norms[idx & 511];
}

// ---------------- launch ----------------
extern "C" void kernel_launch(void* const* d_in, const int* in_sizes, int n_in,
                              void* d_out, int out_size) {
    const float* x = (const float*)d_in[0];
    const int* eidx = (const int*)d_in[1];
    const int* clu = (const int*)d_in[2];
    int base = n_in - 18;
    const float* P[18];
    for (int i = 0; i < 18; i++) P[i] = (const float*)d_in[base + i];
    const int* src = eidx;
    const int* dst = eidx + N_EDGES;
    float* out = (float*)d_out;

    // R11-optimal tile config + work-stealing task loop.
    constexpr int NW = 16;
    constexpr int NB0 = 8, NB1 = 8, NB2 = 6;
    const int smem0 = (64 * 128 + NW * NB0 * 64) * 4;    //  65536
    const int smem1 = (128 * 128 + NW * NB1 * 128) * 4;  // 131072
    const int smem2 = (256 * 128 + NW * NB2 * 256) * 4;  // 229376
    cudaFuncSetAttribute(mlp_k<64, NW, NB0>,  cudaFuncAttributeMaxDynamicSharedMemorySize, smem0);
    cudaFuncSetAttribute(mlp_k<128, NW, NB1>, cudaFuncAttributeMaxDynamicSharedMemorySize, smem1);
    cudaFuncSetAttribute(mlp_k<256, NW, NB2>, cudaFuncAttributeMaxDynamicSharedMemorySize, smem2);

    // CSR build interleaved with layer-0 MLP (mlp0 at launch #4 for ncu sampling)
    zero_counts_k<<<196, 256>>>();
    hist_k<<<3125, 256>>>(dst, clu);
    scan_p1_k<<<NBLK_N + NBLK_C, 256>>>();
    mlp_k<64, NW, NB0><<<GRID_SMS, NW * 32, smem0>>>(x, P[0], P[1], P[2], P[3], P[4], P[5]);
    scan_p3_k<<<NBLK_N + NBLK_C, 256>>>();
    fill_k<<<3125, 256>>>(src, dst, clu);

    const int aggBlocks = (N_NODES * 32 + 255) / 256;

    agg_k<64><<<aggBlocks, 256>>>();
    mlp_k<128, NW, NB1><<<GRID_SMS, NW * 32, smem1>>>(x, P[6], P[7], P[8], P[9], P[10], P[11]);
    agg_k<128><<<aggBlocks, 256>>>();
    mlp_k<256, NW, NB2><<<GRID_SMS, NW * 32, smem2>>>(x, P[12], P[13], P[14], P[15], P[16], P[17]);

    // fused layer-2 scatter-max + cluster pool, then column L2 normalization
    pool_fused_k<<<(N_CLUST * 32 + 255) / 256, 256>>>();
    colsum_k<<<64, 512>>>();
    norm_k<<<1, 512>>>();
    scale_k<<<(N_CLUST * 512 + 255) / 256, 256>>>(out);
}

// round 14
// speedup vs baseline: 1.0813x; 1.0813x over previous
#include <cuda_runtime.h>
#include <cuda_fp16.h>
#include <math.h>
#include <stdint.h>

#define N_NODES 50000
#define N_EDGES 800000
#define N_CLUST 5000
#define GRID_SMS 152
#define NBLK_N 49   // ceil(50000/1024)
#define NBLK_C 5    // ceil(5000/1024)

// ---------------- static device scratch ----------------
__device__ __align__(16) float g_x1[N_NODES * 128];
__device__ __align__(16) float g_x2[N_NODES * 256];
__device__ __align__(16) float g_x3[N_NODES * 512];
__device__ __align__(16) __half g_h1[N_NODES * 64];    // fp16 copy of h (layer0)
__device__ __align__(16) __half g_h2[N_NODES * 128];   // layer1
__device__ __align__(16) __half g_h3[N_NODES * 256];   // layer2
__device__ __align__(16) float g_pooled[N_CLUST * 512];
__device__ __align__(16) float g_partial[64 * 512];
__device__ __align__(16) float g_norms[512];

__device__ int g_deg[N_NODES];
__device__ int g_rowptr[N_NODES + 1];
__device__ int g_cursor[N_NODES];
__device__ int g_esrc[N_EDGES];
__device__ int g_cdeg[N_CLUST];
__device__ int g_crow[N_CLUST + 1];
__device__ int g_ccur[N_CLUST];
__device__ int g_cnodes[N_NODES];
__device__ int g_bsumN[NBLK_N];
__device__ int g_bsumC[NBLK_C];
__device__ int g_task[3];   // work-stealing counters; reset by scale_k each run

__device__ __forceinline__ float4 fmax4(float4 a, float4 b) {
    return make_float4(fmaxf(a.x, b.x), fmaxf(a.y, b.y), fmaxf(a.z, b.z), fmaxf(a.w, b.w));
}
__device__ __forceinline__ unsigned h2u(__half2 h) {
    return *reinterpret_cast<unsigned*>(&h);
}

// ---------------- CSR build ----------------
__global__ void zero_counts_k() {
    int i = blockIdx.x * blockDim.x + threadIdx.x;
    if (i < N_NODES) g_deg[i] = 0;
    if (i < N_CLUST) g_cdeg[i] = 0;
    // NOTE: g_task NOT zeroed here (would race with concurrent mlp0 on the
    // other stream); scale_k resets it at the end of every run.
}

__global__ void hist_k(const int* __restrict__ dst, const int* __restrict__ clu) {
    int i = blockIdx.x * blockDim.x + threadIdx.x;
    if (i < N_EDGES) atomicAdd(&g_deg[dst[i]], 1);
    if (i < N_NODES) atomicAdd(&g_cdeg[clu[i]], 1);
}

// phase 1: per-1024-chunk sums. grid = NBLK_N + NBLK_C, 256 threads
__global__ void scan_p1_k() {
    int blk = blockIdx.x, t = threadIdx.x;
    const int* in; int n, lb;
    if (blk < NBLK_N) { in = g_deg;  n = N_NODES; lb = blk; }
    else              { in = g_cdeg; n = N_CLUST; lb = blk - NBLK_N; }
    int i0 = lb * 1024 + t * 4;
    int s = 0;
#pragma unroll
    for (int u = 0; u < 4; u++) if (i0 + u < n) s += in[i0 + u];
    int lane = t & 31, w = t >> 5;
#pragma unroll
    for (int o = 16; o > 0; o >>= 1) s += __shfl_down_sync(0xffffffffu, s, o);
    __shared__ int wt[8];
    if (lane == 0) wt[w] = s;
    __syncthreads();
    if (t == 0) {
        int tot = 0;
#pragma unroll
        for (int i = 0; i < 8; i++) tot += wt[i];
        if (blk < NBLK_N) g_bsumN[lb] = tot; else g_bsumC[lb] = tot;
    }
}

// phase 3 (p2 fused): block computes its own base, does local scan, writes
// rowptr AND cursor; the thread holding the final element writes out[n].
__global__ void scan_p3_k() {
    int blk = blockIdx.x, t = threadIdx.x;
    const int* in; int* outp; int* cur; const int* bs; int n, lb;
    if (blk < NBLK_N) { in = g_deg;  outp = g_rowptr; cur = g_cursor; bs = g_bsumN; n = N_NODES; lb = blk; }
    else              { in = g_cdeg; outp = g_crow;   cur = g_ccur;   bs = g_bsumC; n = N_CLUST; lb = blk - NBLK_N; }
    __shared__ int sbase;
    if (t == 0) {
        int s = 0;
        for (int i = 0; i < lb; i++) s += bs[i];
        sbase = s;
    }
    int i0 = lb * 1024 + t * 4;
    int v[4];
#pragma unroll
    for (int u = 0; u < 4; u++) v[u] = (i0 + u < n) ? in[i0 + u] : 0;
    int ts = v[0] + v[1] + v[2] + v[3];
    int lane = t & 31, w = t >> 5;
    int s = ts;
#pragma unroll
    for (int o = 1; o < 32; o <<= 1) {
        int x = __shfl_up_sync(0xffffffffu, s, o);
        if (lane >= o) s += x;
    }
    __shared__ int wt[8], wte[8];
    if (lane == 31) wt[w] = s;
    __syncthreads();
    if (t < 8) { int e = 0; for (int i = 0; i < t; i++) e += wt[i]; wte[t] = e; }
    __syncthreads();
    int run = s - ts + wte[w] + sbase;
#pragma unroll
    for (int u = 0; u < 4; u++) {
        if (i0 + u < n) {
            outp[i0 + u] = run; cur[i0 + u] = run;
            run += v[u];
            if (i0 + u == n - 1) outp[n] = run;
        }
    }
}

__global__ void fill_k(const int* __restrict__ src, const int* __restrict__ dst,
                       const int* __restrict__ clu) {
    int i = blockIdx.x * blockDim.x + threadIdx.x;
    if (i < N_EDGES) {
        int slot = atomicAdd(&g_cursor[dst[i]], 1);
        g_esrc[slot] = src[i];
    }
    if (i < N_NODES) {
        int slot = atomicAdd(&g_ccur[clu[i]], 1);
        g_cnodes[slot] = i;
    }
}

// ---------------- per-node MLP: Linear(CIN->64) -> LN -> ReLU -> Linear(64->CIN) ----------------
// Work-stealing task loop (atomic counter) removes the static-schedule tail.
// Epilogue also writes an fp16 copy of h for the AGG gathers.
template <int CIN, int NW, int NB>
__global__ void __launch_bounds__(NW * 32, 1) mlp_k(
    const float* __restrict__ xin_ext,
    const float* __restrict__ w1, const float* __restrict__ b1,
    const float* __restrict__ gg, const float* __restrict__ be,
    const float* __restrict__ w2, const float* __restrict__ b2)
{
    constexpr int CPL = CIN / 32;
    constexpr int LIDX = (CIN == 64) ? 0 : (CIN == 128) ? 1 : 2;
    const float* xin;
    float* xout;
    __half* hbuf;
    if constexpr (CIN == 64)       { xin = xin_ext; xout = g_x1; hbuf = g_h1; }
    else if constexpr (CIN == 128) { xin = g_x1;    xout = g_x2; hbuf = g_h2; }
    else                           { xin = g_x2;    xout = g_x3; hbuf = g_h3; }

    extern __shared__ float smem[];
    float* w1s = smem;             // [CIN][64]
    float* w2s = smem + CIN * 64;  // [64][CIN]
    int tid = threadIdx.x;
    int L = tid & 31;
    int w = tid >> 5;
    float* xs = smem + CIN * 128 + w * (NB * CIN);

    for (int i = tid; i < CIN * 64; i += NW * 32) { w1s[i] = w1[i]; w2s[i] = w2[i]; }
    __syncthreads();

    float b1a = b1[2 * L], b1b = b1[2 * L + 1];
    float ga = gg[2 * L], gb = gg[2 * L + 1];
    float bea = be[2 * L], beb = be[2 * L + 1];
    float b2r[CPL];
#pragma unroll
    for (int k = 0; k < CPL; k++) b2r[k] = b2[CPL * L + k];

    const int ntasks = (N_NODES + NB - 1) / NB;
    while (true) {
        int task;
        if (L == 0) task = atomicAdd(&g_task[LIDX], 1);
        task = __shfl_sync(0xffffffffu, task, 0);
        if (task >= ntasks) break;
        int n0 = task * NB;
#pragma unroll
        for (int b = 0; b < NB; b++) {
            int n = n0 + b;
            if (n < N_NODES) {
                const float4* xr = reinterpret_cast<const float4*>(xin + (size_t)n * CIN);
                float4* xd = reinterpret_cast<float4*>(xs + b * CIN);
                for (int k = L; k < CIN / 4; k += 32) xd[k] = xr[k];
            }
        }
        __syncwarp();

        // ---- h = x @ w1 + b1 ----
        float a0[NB], a1[NB];
#pragma unroll
        for (int b = 0; b < NB; b++) { a0[b] = b1a; a1[b] = b1b; }
#pragma unroll 2
        for (int c = 0; c < CIN; c += 4) {
            float4 xv[NB];
#pragma unroll
            for (int b = 0; b < NB; b++) xv[b] = *reinterpret_cast<const float4*>(&xs[b * CIN + c]);
#pragma unroll
            for (int u = 0; u < 4; u++) {
                float2 wv = *reinterpret_cast<const float2*>(&w1s[(c + u) * 64 + 2 * L]);
#pragma unroll
                for (int b = 0; b < NB; b++) {
                    float xb = (u == 0) ? xv[b].x : (u == 1) ? xv[b].y : (u == 2) ? xv[b].z : xv[b].w;
                    a0[b] = fmaf(xb, wv.x, a0[b]);
                    a1[b] = fmaf(xb, wv.y, a1[b]);
                }
            }
        }

        // ---- LayerNorm(64) + ReLU ----
        float h0[NB], h1[NB];
#pragma unroll
        for (int b = 0; b < NB; b++) {
            float s = a0[b] + a1[b];
#pragma unroll
            for (int o = 16; o > 0; o >>= 1) s += __shfl_xor_sync(0xffffffffu, s, o);
            float mu = s * (1.0f / 64.0f);
            float e0 = a0[b] - mu, e1 = a1[b] - mu;
            float q = e0 * e0 + e1 * e1;
#pragma unroll
            for (int o = 16; o > 0; o >>= 1) q += __shfl_xor_sync(0xffffffffu, q, o);
            float rs = rsqrtf(q * (1.0f / 64.0f) + 1e-5f);
            h0[b] = fmaxf(fmaf(e0 * rs, ga, bea), 0.0f);
            h1[b] = fmaxf(fmaf(e1 * rs, gb, beb), 0.0f);
        }
        __syncwarp();
#pragma unroll
        for (int b = 0; b < NB; b++)
            *reinterpret_cast<float2*>(&xs[b * CIN + 2 * L]) = make_float2(h0[b], h1[b]);
        __syncwarp();

        // ---- out = h @ w2 + b2 ----
        float acc[NB][CPL];
#pragma unroll
        for (int b = 0; b < NB; b++)
#pragma unroll
            for (int k = 0; k < CPL; k++) acc[b][k] = b2r[k];

#pragma unroll 2
        for (int j = 0; j < 64; j += 4) {
            float4 hv[NB];
#pragma unroll
            for (int b = 0; b < NB; b++) hv[b] = *reinterpret_cast<const float4*>(&xs[b * CIN + j]);
#pragma unroll
            for (int u = 0; u < 4; u++) {
                if constexpr (CPL >= 4) {
#pragma unroll
                    for (int k = 0; k < CPL; k += 4) {
                        float4 wv = *reinterpret_cast<const float4*>(&w2s[(j + u) * CIN + CPL * L + k]);
#pragma unroll
                        for (int b = 0; b < NB; b++) {
                            float hb = (u == 0) ? hv[b].x : (u == 1) ? hv[b].y : (u == 2) ? hv[b].z : hv[b].w;
                            acc[b][k + 0] = fmaf(hb, wv.x, acc[b][k + 0]);
                            acc[b][k + 1] = fmaf(hb, wv.y, acc[b][k + 1]);
                            acc[b][k + 2] = fmaf(hb, wv.z, acc[b][k + 2]);
                            acc[b][k + 3] = fmaf(hb, wv.w, acc[b][k + 3]);
                        }
                    }
                } else {
                    float2 wv = *reinterpret_cast<const float2*>(&w2s[(j + u) * CIN + 2 * L]);
#pragma unroll
                    for (int b = 0; b < NB; b++) {
                        float hb = (u == 0) ? hv[b].x : (u == 1) ? hv[b].y : (u == 2) ? hv[b].z : hv[b].w;
                        acc[b][0] = fmaf(hb, wv.x, acc[b][0]);
                        acc[b][1] = fmaf(hb, wv.y, acc[b][1]);
                    }
                }
            }
        }

#pragma unroll
        for (int b = 0; b < NB; b++) {
            int n = n0 + b;
            if (n < N_NODES) {
                float* orow = xout + (size_t)n * (2 * CIN) + CPL * L;
                __half* hrow = hbuf + (size_t)n * CIN + CPL * L;
                if constexpr (CPL == 2) {
                    *reinterpret_cast<float2*>(orow) = make_float2(acc[b][0], acc[b][1]);
                    *reinterpret_cast<unsigned*>(hrow) =
                        h2u(__floats2half2_rn(acc[b][0], acc[b][1]));
                } else if constexpr (CPL == 4) {
                    *reinterpret_cast<float4*>(orow) =
                        make_float4(acc[b][0], acc[b][1], acc[b][2], acc[b][3]);
                    uint2 hp;
                    hp.x = h2u(__floats2half2_rn(acc[b][0], acc[b][1]));
                    hp.y = h2u(__floats2half2_rn(acc[b][2], acc[b][3]));
                    *reinterpret_cast<uint2*>(hrow) = hp;
                } else {
#pragma unroll
                    for (int k = 0; k < CPL; k += 4)
                        *reinterpret_cast<float4*>(orow + k) =
                            make_float4(acc[b][k], acc[b][k + 1], acc[b][k + 2], acc[b][k + 3]);
                    uint4 hp;
                    hp.x = h2u(__floats2half2_rn(acc[b][0], acc[b][1]));
                    hp.y = h2u(__floats2half2_rn(acc[b][2], acc[b][3]));
                    hp.z = h2u(__floats2half2_rn(acc[b][4], acc[b][5]));
                    hp.w = h2u(__floats2half2_rn(acc[b][6], acc[b][7]));
                    *reinterpret_cast<uint4*>(hrow) = hp;
                }
            }
        }
        __syncwarp();
    }
}

// ---------------- scatter-max via CSR gather (fp16 rows): warp per dst node ----------------
// max over fp16(h) == fp16(max over h) exactly (RN conversion is monotonic).
template <int CIN>
__global__ void agg_k() {
    constexpr int CPL = CIN / 32;   // halves per lane
    constexpr int H2 = CPL / 2;     // half2 per lane
    const __half* hbuf; float* xout;
    if constexpr (CIN == 64)       { hbuf = g_h1; xout = g_x1; }
    else if constexpr (CIN == 128) { hbuf = g_h2; xout = g_x2; }
    else                           { hbuf = g_h3; xout = g_x3; }

    int gw = (blockIdx.x * blockDim.x + threadIdx.x) >> 5;
    int L = threadIdx.x & 31;
    if (gw >= N_NODES) return;
    int beg = g_rowptr[gw], end = g_rowptr[gw + 1];
    const __half2 NEGH = __half2half2(__ushort_as_half((unsigned short)0xFC00));  // -inf,-inf

    __half2 m[H2];
#pragma unroll
    for (int k = 0; k < H2; k++) m[k] = NEGH;

    int e = beg;
    for (; e + 2 <= end; e += 2) {
        int s0 = g_esrc[e], s1 = g_esrc[e + 1];
        const __half* p0 = hbuf + (size_t)s0 * CIN + CPL * L;
        const __half* p1 = hbuf + (size_t)s1 * CIN + CPL * L;
        if constexpr (H2 == 1) {
            __half2 v0 = *reinterpret_cast<const __half2*>(p0);
            __half2 v1 = *reinterpret_cast<const __half2*>(p1);
            m[0] = __hmax2(m[0], __hmax2(v0, v1));
        } else if constexpr (H2 == 2) {
            uint2 r0 = *reinterpret_cast<const uint2*>(p0);
            uint2 r1 = *reinterpret_cast<const uint2*>(p1);
            const __half2* a = reinterpret_cast<const __half2*>(&r0);
            const __half2* b = reinterpret_cast<const __half2*>(&r1);
#pragma unroll
            for (int k = 0; k < 2; k++) m[k] = __hmax2(m[k], __hmax2(a[k], b[k]));
        } else {
            uint4 r0 = *reinterpret_cast<const uint4*>(p0);
            uint4 r1 = *reinterpret_cast<const uint4*>(p1);
            const __half2* a = reinterpret_cast<const __half2*>(&r0);
            const __half2* b = reinterpret_cast<const __half2*>(&r1);
#pragma unroll
            for (int k = 0; k < 4; k++) m[k] = __hmax2(m[k], __hmax2(a[k], b[k]));
        }
    }
    if (e < end) {
        int s0 = g_esrc[e];
        const __half* p0 = hbuf + (size_t)s0 * CIN + CPL * L;
        if constexpr (H2 == 1) {
            m[0] = __hmax2(m[0], *reinterpret_cast<const __half2*>(p0));
        } else if constexpr (H2 == 2) {
            uint2 r0 = *reinterpret_cast<const uint2*>(p0);
            const __half2* a = reinterpret_cast<const __half2*>(&r0);
#pragma unroll
            for (int k = 0; k < 2; k++) m[k] = __hmax2(m[k], a[k]);
        } else {
            uint4 r0 = *reinterpret_cast<const uint4*>(p0);
            const __half2* a = reinterpret_cast<const __half2*>(&r0);
#pragma unroll
            for (int k = 0; k < 4; k++) m[k] = __hmax2(m[k], a[k]);
        }
    }

    float* orow = xout + (size_t)gw * (2 * CIN) + CIN + CPL * L;
    bool empty = (beg == end);
    if constexpr (H2 == 1) {
        float2 f = empty ? make_float2(0.f, 0.f) : __half22float2(m[0]);
        *reinterpret_cast<float2*>(orow) = f;
    } else if constexpr (H2 == 2) {
        float2 f0 = empty ? make_float2(0.f, 0.f) : __half22float2(m[0]);
        float2 f1 = empty ? make_float2(0.f, 0.f) : __half22float2(m[1]);
        *reinterpret_cast<float4*>(orow) = make_float4(f0.x, f0.y, f1.x, f1.y);
    } else {
#pragma unroll
        for (int k = 0; k < 4; k += 2) {
            float2 f0 = empty ? make_float2(0.f, 0.f) : __half22float2(m[k]);
            float2 f1 = empty ? make_float2(0.f, 0.f) : __half22float2(m[k + 1]);
            *reinterpret_cast<float4*>(orow + 2 * k) = make_float4(f0.x, f0.y, f1.x, f1.y);
        }
    }
}

// ---------------- cluster max-pool ----------------
__global__ void pool_k() {
    int gw = (blockIdx.x * blockDim.x + threadIdx.x) >> 5;
    int L = threadIdx.x & 31;
    if (gw >= N_CLUST) return;
    int beg = g_crow[gw], end = g_crow[gw + 1];
    const float NEG = __int_as_float(0xff800000);
    float4 m[4];
#pragma unroll
    for (int k = 0; k < 4; k++) m[k] = make_float4(NEG, NEG, NEG, NEG);
    for (int e = beg; e < end; e++) {
        int n = g_cnodes[e];
        const float4* r = reinterpret_cast<const float4*>(g_x3 + (size_t)n * 512 + 16 * L);
#pragma unroll
        for (int k = 0; k < 4; k++) m[k] = fmax4(m[k], r[k]);
    }
    if (beg == end) {
#pragma unroll
        for (int k = 0; k < 4; k++) m[k] = make_float4(0.f, 0.f, 0.f, 0.f);
    }
    float4* o = reinterpret_cast<float4*>(g_pooled + (size_t)gw * 512 + 16 * L);
#pragma unroll
    for (int k = 0; k < 4; k++) o[k] = m[k];
}

// ---------------- column L2 norm + scale ----------------
__global__ void colsum_k() {
    int b = blockIdx.x, c = threadIdx.x;
    int per = (N_CLUST + 63) / 64;
    int r0 = b * per;
    int r1 = r0 + per; if (r1 > N_CLUST) r1 = N_CLUST;
    float s = 0.0f;
    for (int r = r0; r < r1; r++) {
        float v = g_pooled[(size_t)r * 512 + c];
        s = fmaf(v, v, s);
    }
    g_partial[b * 512 + c] = s;
}

__global__ void norm_k() {
    int c = threadIdx.x;
    float s = 0.0f;
    for (int b = 0; b < 64; b++) s += g_partial[b * 512 + c];
    g_norms[c] = sqrtf(s);
}

__global__ void scale_k(float* __restrict__ out) {
    int idx = blockIdx.x * blockDim.x + threadIdx.x;
    if (idx < N_CLUST * 512) out[idx] = g_pooled[idx] / g_norms[idx & 511];
    if (idx < 3) g_task[idx] = 0;   // reset work-stealing counters for next replay
}

// ---------------- launch ----------------
extern "C" void kernel_launch(void* const* d_in, const int* in_sizes, int n_in,
                              void* d_out, int out_size) {
    const float* x = (const float*)d_in[0];
    const int* eidx = (const int*)d_in[1];
    const int* clu = (const int*)d_in[2];
    int base = n_in - 18;
    const float* P[18];
    for (int i = 0; i < 18; i++) P[i] = (const float*)d_in[base + i];
    const int* src = eidx;
    const int* dst = eidx + N_EDGES;
    float* out = (float*)d_out;

    constexpr int NW = 16;
    constexpr int NB0 = 8, NB1 = 8, NB2 = 6;
    const int smem0 = (64 * 128 + NW * NB0 * 64) * 4;    //  65536
    const int smem1 = (128 * 128 + NW * NB1 * 128) * 4;  // 131072
    const int smem2 = (256 * 128 + NW * NB2 * 256) * 4;  // 229376
    cudaFuncSetAttribute(mlp_k<64, NW, NB0>,  cudaFuncAttributeMaxDynamicSharedMemorySize, smem0);
    cudaFuncSetAttribute(mlp_k<128, NW, NB1>, cudaFuncAttributeMaxDynamicSharedMemorySize, smem1);
    cudaFuncSetAttribute(mlp_k<256, NW, NB2>, cudaFuncAttributeMaxDynamicSharedMemorySize, smem2);

    // Fork: CSR build (side stream) overlaps mlp0 (NULL stream) — disjoint buffers.
    cudaStream_t s2;
    cudaStreamCreateWithFlags(&s2, cudaStreamNonBlocking);
    cudaEvent_t eFork, eJoin;
    cudaEventCreateWithFlags(&eFork, cudaEventDisableTiming);
    cudaEventCreateWithFlags(&eJoin, cudaEventDisableTiming);

    cudaEventRecord(eFork, 0);
    cudaStreamWaitEvent(s2, eFork, 0);

    // side stream: CSR build chain
    zero_counts_k<<<196, 256, 0, s2>>>();
    hist_k<<<3125, 256, 0, s2>>>(dst, clu);
    scan_p1_k<<<NBLK_N + NBLK_C, 256, 0, s2>>>();
    scan_p3_k<<<NBLK_N + NBLK_C, 256, 0, s2>>>();
    fill_k<<<3125, 256, 0, s2>>>(src, dst, clu);
    cudaEventRecord(eJoin, s2);

    // NULL stream: layer-0 MLP (depends only on x + weights)
    mlp_k<64, NW, NB0><<<GRID_SMS, NW * 32, smem0>>>(x, P[0], P[1], P[2], P[3], P[4], P[5]);

    // join: agg needs CSR + h1
    cudaStreamWaitEvent(0, eJoin, 0);

    const int aggBlocks = (N_NODES * 32 + 255) / 256;

    agg_k<64><<<aggBlocks, 256>>>();
    mlp_k<128, NW, NB1><<<GRID_SMS, NW * 32, smem1>>>(x, P[6], P[7], P[8], P[9], P[10], P[11]);
    agg_k<128><<<aggBlocks, 256>>>();
    mlp_k<256, NW, NB2><<<GRID_SMS, NW * 32, smem2>>>(x, P[12], P[13], P[14], P[15], P[16], P[17]);
    agg_k<256><<<aggBlocks, 256>>>();

    pool_k<<<(N_CLUST * 32 + 255) / 256, 256>>>();
    colsum_k<<<64, 512>>>();
    norm_k<<<1, 512>>>();
    scale_k<<<(N_CLUST * 512 + 255) / 256, 256>>>(out);

    cudaEventDestroy(eFork);
    cudaEventDestroy(eJoin);
    cudaStreamDestroy(s2);
}

// round 15
// speedup vs baseline: 1.0854x; 1.0038x over previous
#include <cuda_runtime.h>
#include <cuda_fp16.h>
#include <math.h>
#include <stdint.h>

#define N_NODES 50000
#define N_EDGES 800000
#define N_CLUST 5000
#define GRID_SMS 152
#define NBLK_N 49   // ceil(50000/1024)
#define NBLK_C 5    // ceil(5000/1024)

// ---------------- static device scratch ----------------
__device__ __align__(16) float g_x1[N_NODES * 128];
__device__ __align__(16) float g_x2[N_NODES * 256];
__device__ __align__(16) float g_x3[N_NODES * 512];
__device__ __align__(16) __half g_h1[N_NODES * 64];    // fp16 copy of h (layer0)
__device__ __align__(16) __half g_h2[N_NODES * 128];   // layer1
__device__ __align__(16) __half g_h3[N_NODES * 256];   // layer2
__device__ __align__(16) float g_pooled[N_CLUST * 512];
__device__ __align__(16) float g_partial[64 * 512];
__device__ __align__(16) float g_norms[512];

__device__ int g_deg[N_NODES];
__device__ int g_rowptr[N_NODES + 1];
__device__ int g_cursor[N_NODES];
__device__ int g_esrc[N_EDGES];
__device__ int g_cdeg[N_CLUST];
__device__ int g_crow[N_CLUST + 1];
__device__ int g_ccur[N_CLUST];
__device__ int g_cnodes[N_NODES];
__device__ int g_bsumN[NBLK_N];
__device__ int g_bsumC[NBLK_C];
__device__ int g_task[3];   // work-stealing counters; reset by scale_k each run

__device__ __forceinline__ float4 fmax4(float4 a, float4 b) {
    return make_float4(fmaxf(a.x, b.x), fmaxf(a.y, b.y), fmaxf(a.z, b.z), fmaxf(a.w, b.w));
}
__device__ __forceinline__ unsigned h2u(__half2 h) {
    return *reinterpret_cast<unsigned*>(&h);
}

// ---------------- CSR build ----------------
__global__ void zero_counts_k() {
    int i = blockIdx.x * blockDim.x + threadIdx.x;
    if (i < N_NODES) g_deg[i] = 0;
    if (i < N_CLUST) g_cdeg[i] = 0;
    // g_task reset happens in scale_k (avoids race with concurrent mlp0)
}

__global__ void hist_k(const int* __restrict__ dst, const int* __restrict__ clu) {
    int i = blockIdx.x * blockDim.x + threadIdx.x;
    if (i < N_EDGES) atomicAdd(&g_deg[dst[i]], 1);
    if (i < N_NODES) atomicAdd(&g_cdeg[clu[i]], 1);
}

__global__ void scan_p1_k() {
    int blk = blockIdx.x, t = threadIdx.x;
    const int* in; int n, lb;
    if (blk < NBLK_N) { in = g_deg;  n = N_NODES; lb = blk; }
    else              { in = g_cdeg; n = N_CLUST; lb = blk - NBLK_N; }
    int i0 = lb * 1024 + t * 4;
    int s = 0;
#pragma unroll
    for (int u = 0; u < 4; u++) if (i0 + u < n) s += in[i0 + u];
    int lane = t & 31, w = t >> 5;
#pragma unroll
    for (int o = 16; o > 0; o >>= 1) s += __shfl_down_sync(0xffffffffu, s, o);
    __shared__ int wt[8];
    if (lane == 0) wt[w] = s;
    __syncthreads();
    if (t == 0) {
        int tot = 0;
#pragma unroll
        for (int i = 0; i < 8; i++) tot += wt[i];
        if (blk < NBLK_N) g_bsumN[lb] = tot; else g_bsumC[lb] = tot;
    }
}

__global__ void scan_p3_k() {
    int blk = blockIdx.x, t = threadIdx.x;
    const int* in; int* outp; int* cur; const int* bs; int n, lb;
    if (blk < NBLK_N) { in = g_deg;  outp = g_rowptr; cur = g_cursor; bs = g_bsumN; n = N_NODES; lb = blk; }
    else              { in = g_cdeg; outp = g_crow;   cur = g_ccur;   bs = g_bsumC; n = N_CLUST; lb = blk - NBLK_N; }
    __shared__ int sbase;
    if (t == 0) {
        int s = 0;
        for (int i = 0; i < lb; i++) s += bs[i];
        sbase = s;
    }
    int i0 = lb * 1024 + t * 4;
    int v[4];
#pragma unroll
    for (int u = 0; u < 4; u++) v[u] = (i0 + u < n) ? in[i0 + u] : 0;
    int ts = v[0] + v[1] + v[2] + v[3];
    int lane = t & 31, w = t >> 5;
    int s = ts;
#pragma unroll
    for (int o = 1; o < 32; o <<= 1) {
        int x = __shfl_up_sync(0xffffffffu, s, o);
        if (lane >= o) s += x;
    }
    __shared__ int wt[8], wte[8];
    if (lane == 31) wt[w] = s;
    __syncthreads();
    if (t < 8) { int e = 0; for (int i = 0; i < t; i++) e += wt[i]; wte[t] = e; }
    __syncthreads();
    int run = s - ts + wte[w] + sbase;
#pragma unroll
    for (int u = 0; u < 4; u++) {
        if (i0 + u < n) {
            outp[i0 + u] = run; cur[i0 + u] = run;
            run += v[u];
            if (i0 + u == n - 1) outp[n] = run;
        }
    }
}

__global__ void fill_k(const int* __restrict__ src, const int* __restrict__ dst,
                       const int* __restrict__ clu) {
    int i = blockIdx.x * blockDim.x + threadIdx.x;
    if (i < N_EDGES) {
        int slot = atomicAdd(&g_cursor[dst[i]], 1);
        g_esrc[slot] = src[i];
    }
    if (i < N_NODES) {
        int slot = atomicAdd(&g_ccur[clu[i]], 1);
        g_cnodes[slot] = i;
    }
}

// ---------------- per-node MLP (layers 0/1): full-row staging ----------------
template <int CIN, int NW, int NB>
__global__ void __launch_bounds__(NW * 32, 1) mlp_k(
    const float* __restrict__ xin_ext,
    const float* __restrict__ w1, const float* __restrict__ b1,
    const float* __restrict__ gg, const float* __restrict__ be,
    const float* __restrict__ w2, const float* __restrict__ b2)
{
    constexpr int CPL = CIN / 32;
    constexpr int LIDX = (CIN == 64) ? 0 : 1;
    const float* xin;
    float* xout;
    __half* hbuf;
    if constexpr (CIN == 64)       { xin = xin_ext; xout = g_x1; hbuf = g_h1; }
    else                           { xin = g_x1;    xout = g_x2; hbuf = g_h2; }

    extern __shared__ float smem[];
    float* w1s = smem;             // [CIN][64]
    float* w2s = smem + CIN * 64;  // [64][CIN]
    int tid = threadIdx.x;
    int L = tid & 31;
    int w = tid >> 5;
    float* xs = smem + CIN * 128 + w * (NB * CIN);

    for (int i = tid; i < CIN * 64; i += NW * 32) { w1s[i] = w1[i]; w2s[i] = w2[i]; }
    __syncthreads();

    float b1a = b1[2 * L], b1b = b1[2 * L + 1];
    float ga = gg[2 * L], gb = gg[2 * L + 1];
    float bea = be[2 * L], beb = be[2 * L + 1];
    float b2r[CPL];
#pragma unroll
    for (int k = 0; k < CPL; k++) b2r[k] = b2[CPL * L + k];

    const int ntasks = (N_NODES + NB - 1) / NB;
    while (true) {
        int task;
        if (L == 0) task = atomicAdd(&g_task[LIDX], 1);
        task = __shfl_sync(0xffffffffu, task, 0);
        if (task >= ntasks) break;
        int n0 = task * NB;
#pragma unroll
        for (int b = 0; b < NB; b++) {
            int n = n0 + b;
            if (n < N_NODES) {
                const float4* xr = reinterpret_cast<const float4*>(xin + (size_t)n * CIN);
                float4* xd = reinterpret_cast<float4*>(xs + b * CIN);
                for (int k = L; k < CIN / 4; k += 32) xd[k] = xr[k];
            }
        }
        __syncwarp();

        float a0[NB], a1[NB];
#pragma unroll
        for (int b = 0; b < NB; b++) { a0[b] = b1a; a1[b] = b1b; }
#pragma unroll 2
        for (int c = 0; c < CIN; c += 4) {
            float4 xv[NB];
#pragma unroll
            for (int b = 0; b < NB; b++) xv[b] = *reinterpret_cast<const float4*>(&xs[b * CIN + c]);
#pragma unroll
            for (int u = 0; u < 4; u++) {
                float2 wv = *reinterpret_cast<const float2*>(&w1s[(c + u) * 64 + 2 * L]);
#pragma unroll
                for (int b = 0; b < NB; b++) {
                    float xb = (u == 0) ? xv[b].x : (u == 1) ? xv[b].y : (u == 2) ? xv[b].z : xv[b].w;
                    a0[b] = fmaf(xb, wv.x, a0[b]);
                    a1[b] = fmaf(xb, wv.y, a1[b]);
                }
            }
        }

        float h0[NB], h1[NB];
#pragma unroll
        for (int b = 0; b < NB; b++) {
            float s = a0[b] + a1[b];
#pragma unroll
            for (int o = 16; o > 0; o >>= 1) s += __shfl_xor_sync(0xffffffffu, s, o);
            float mu = s * (1.0f / 64.0f);
            float e0 = a0[b] - mu, e1 = a1[b] - mu;
            float q = e0 * e0 + e1 * e1;
#pragma unroll
            for (int o = 16; o > 0; o >>= 1) q += __shfl_xor_sync(0xffffffffu, q, o);
            float rs = rsqrtf(q * (1.0f / 64.0f) + 1e-5f);
            h0[b] = fmaxf(fmaf(e0 * rs, ga, bea), 0.0f);
            h1[b] = fmaxf(fmaf(e1 * rs, gb, beb), 0.0f);
        }
        __syncwarp();
#pragma unroll
        for (int b = 0; b < NB; b++)
            *reinterpret_cast<float2*>(&xs[b * CIN + 2 * L]) = make_float2(h0[b], h1[b]);
        __syncwarp();

        float acc[NB][CPL];
#pragma unroll
        for (int b = 0; b < NB; b++)
#pragma unroll
            for (int k = 0; k < CPL; k++) acc[b][k] = b2r[k];

#pragma unroll 2
        for (int j = 0; j < 64; j += 4) {
            float4 hv[NB];
#pragma unroll
            for (int b = 0; b < NB; b++) hv[b] = *reinterpret_cast<const float4*>(&xs[b * CIN + j]);
#pragma unroll
            for (int u = 0; u < 4; u++) {
                if constexpr (CPL >= 4) {
#pragma unroll
                    for (int k = 0; k < CPL; k += 4) {
                        float4 wv = *reinterpret_cast<const float4*>(&w2s[(j + u) * CIN + CPL * L + k]);
#pragma unroll
                        for (int b = 0; b < NB; b++) {
                            float hb = (u == 0) ? hv[b].x : (u == 1) ? hv[b].y : (u == 2) ? hv[b].z : hv[b].w;
                            acc[b][k + 0] = fmaf(hb, wv.x, acc[b][k + 0]);
                            acc[b][k + 1] = fmaf(hb, wv.y, acc[b][k + 1]);
                            acc[b][k + 2] = fmaf(hb, wv.z, acc[b][k + 2]);
                            acc[b][k + 3] = fmaf(hb, wv.w, acc[b][k + 3]);
                        }
                    }
                } else {
                    float2 wv = *reinterpret_cast<const float2*>(&w2s[(j + u) * CIN + 2 * L]);
#pragma unroll
                    for (int b = 0; b < NB; b++) {
                        float hb = (u == 0) ? hv[b].x : (u == 1) ? hv[b].y : (u == 2) ? hv[b].z : hv[b].w;
                        acc[b][0] = fmaf(hb, wv.x, acc[b][0]);
                        acc[b][1] = fmaf(hb, wv.y, acc[b][1]);
                    }
                }
            }
        }

#pragma unroll
        for (int b = 0; b < NB; b++) {
            int n = n0 + b;
            if (n < N_NODES) {
                float* orow = xout + (size_t)n * (2 * CIN) + CPL * L;
                __half* hrow = hbuf + (size_t)n * CIN + CPL * L;
                if constexpr (CPL == 2) {
                    *reinterpret_cast<float2*>(orow) = make_float2(acc[b][0], acc[b][1]);
                    *reinterpret_cast<unsigned*>(hrow) =
                        h2u(__floats2half2_rn(acc[b][0], acc[b][1]));
                } else {
                    *reinterpret_cast<float4*>(orow) =
                        make_float4(acc[b][0], acc[b][1], acc[b][2], acc[b][3]);
                    uint2 hp;
                    hp.x = h2u(__floats2half2_rn(acc[b][0], acc[b][1]));
                    hp.y = h2u(__floats2half2_rn(acc[b][2], acc[b][3]));
                    *reinterpret_cast<uint2*>(hrow) = hp;
                }
            }
        }
        __syncwarp();
    }
}

// ---------------- layer-2 MLP: chunked x-staging (64-col chunks) -> NB=8 ----------------
template <int NW, int NB>
__global__ void __launch_bounds__(NW * 32, 1) mlp2_k(
    const float* __restrict__ w1, const float* __restrict__ b1,
    const float* __restrict__ gg, const float* __restrict__ be,
    const float* __restrict__ w2, const float* __restrict__ b2)
{
    constexpr int CIN = 256, CPL = 8;
    extern __shared__ float smem[];
    float* w1s = smem;              // [256][64]
    float* w2s = smem + CIN * 64;   // [64][256]
    int tid = threadIdx.x;
    int L = tid & 31;
    int w = tid >> 5;
    float* xs = smem + CIN * 128 + w * (NB * 64);  // [NW][NB][64]

    for (int i = tid; i < CIN * 64; i += NW * 32) { w1s[i] = w1[i]; w2s[i] = w2[i]; }
    __syncthreads();

    float b1a = b1[2 * L], b1b = b1[2 * L + 1];
    float ga = gg[2 * L], gb = gg[2 * L + 1];
    float bea = be[2 * L], beb = be[2 * L + 1];
    float b2r[CPL];
#pragma unroll
    for (int k = 0; k < CPL; k++) b2r[k] = b2[CPL * L + k];

    const int ntasks = (N_NODES + NB - 1) / NB;
    while (true) {
        int task;
        if (L == 0) task = atomicAdd(&g_task[2], 1);
        task = __shfl_sync(0xffffffffu, task, 0);
        if (task >= ntasks) break;
        int n0 = task * NB;

        float a0[NB], a1[NB];
#pragma unroll
        for (int b = 0; b < NB; b++) { a0[b] = b1a; a1[b] = b1b; }

#pragma unroll
        for (int ch = 0; ch < 4; ch++) {
            // stage chunk: NB*16 float4s; pos -> (b = pos/16, k = pos%16)
            for (int pos = L; pos < NB * 16; pos += 32) {
                int b = pos >> 4, k = pos & 15;
                int n = n0 + b;
                if (n < N_NODES)
                    *reinterpret_cast<float4*>(&xs[b * 64 + 4 * k]) =
                        *reinterpret_cast<const float4*>(g_x2 + (size_t)n * CIN + ch * 64 + 4 * k);
            }
            __syncwarp();
#pragma unroll 2
            for (int c = 0; c < 64; c += 4) {
                float4 xv[NB];
#pragma unroll
                for (int b = 0; b < NB; b++) xv[b] = *reinterpret_cast<const float4*>(&xs[b * 64 + c]);
#pragma unroll
                for (int u = 0; u < 4; u++) {
                    float2 wv = *reinterpret_cast<const float2*>(&w1s[(ch * 64 + c + u) * 64 + 2 * L]);
#pragma unroll
                    for (int b = 0; b < NB; b++) {
                        float xb = (u == 0) ? xv[b].x : (u == 1) ? xv[b].y : (u == 2) ? xv[b].z : xv[b].w;
                        a0[b] = fmaf(xb, wv.x, a0[b]);
                        a1[b] = fmaf(xb, wv.y, a1[b]);
                    }
                }
            }
            __syncwarp();
        }

        // ---- LayerNorm(64) + ReLU ----
        float h0[NB], h1[NB];
#pragma unroll
        for (int b = 0; b < NB; b++) {
            float s = a0[b] + a1[b];
#pragma unroll
            for (int o = 16; o > 0; o >>= 1) s += __shfl_xor_sync(0xffffffffu, s, o);
            float mu = s * (1.0f / 64.0f);
            float e0 = a0[b] - mu, e1 = a1[b] - mu;
            float q = e0 * e0 + e1 * e1;
#pragma unroll
            for (int o = 16; o > 0; o >>= 1) q += __shfl_xor_sync(0xffffffffu, q, o);
            float rs = rsqrtf(q * (1.0f / 64.0f) + 1e-5f);
            h0[b] = fmaxf(fmaf(e0 * rs, ga, bea), 0.0f);
            h1[b] = fmaxf(fmaf(e1 * rs, gb, beb), 0.0f);
        }
        __syncwarp();
#pragma unroll
        for (int b = 0; b < NB; b++)
            *reinterpret_cast<float2*>(&xs[b * 64 + 2 * L]) = make_float2(h0[b], h1[b]);
        __syncwarp();

        // ---- out = h @ w2 + b2 ----
        float acc[NB][CPL];
#pragma unroll
        for (int b = 0; b < NB; b++)
#pragma unroll
            for (int k = 0; k < CPL; k++) acc[b][k] = b2r[k];

#pragma unroll 2
        for (int j = 0; j < 64; j += 4) {
            float4 hv[NB];
#pragma unroll
            for (int b = 0; b < NB; b++) hv[b] = *reinterpret_cast<const float4*>(&xs[b * 64 + j]);
#pragma unroll
            for (int u = 0; u < 4; u++) {
#pragma unroll
                for (int k = 0; k < CPL; k += 4) {
                    float4 wv = *reinterpret_cast<const float4*>(&w2s[(j + u) * CIN + CPL * L + k]);
#pragma unroll
                    for (int b = 0; b < NB; b++) {
                        float hb = (u == 0) ? hv[b].x : (u == 1) ? hv[b].y : (u == 2) ? hv[b].z : hv[b].w;
                        acc[b][k + 0] = fmaf(hb, wv.x, acc[b][k + 0]);
                        acc[b][k + 1] = fmaf(hb, wv.y, acc[b][k + 1]);
                        acc[b][k + 2] = fmaf(hb, wv.z, acc[b][k + 2]);
                        acc[b][k + 3] = fmaf(hb, wv.w, acc[b][k + 3]);
                    }
                }
            }
        }

#pragma unroll
        for (int b = 0; b < NB; b++) {
            int n = n0 + b;
            if (n < N_NODES) {
                float* orow = g_x3 + (size_t)n * 512 + CPL * L;
                __half* hrow = g_h3 + (size_t)n * CIN + CPL * L;
#pragma unroll
                for (int k = 0; k < CPL; k += 4)
                    *reinterpret_cast<float4*>(orow + k) =
                        make_float4(acc[b][k], acc[b][k + 1], acc[b][k + 2], acc[b][k + 3]);
                uint4 hp;
                hp.x = h2u(__floats2half2_rn(acc[b][0], acc[b][1]));
                hp.y = h2u(__floats2half2_rn(acc[b][2], acc[b][3]));
                hp.z = h2u(__floats2half2_rn(acc[b][4], acc[b][5]));
                hp.w = h2u(__floats2half2_rn(acc[b][6], acc[b][7]));
                *reinterpret_cast<uint4*>(hrow) = hp;
            }
        }
        __syncwarp();
    }
}

// ---------------- scatter-max via CSR gather (fp16 rows): warp per dst node ----------------
template <int CIN>
__global__ void agg_k() {
    constexpr int CPL = CIN / 32;
    constexpr int H2 = CPL / 2;
    const __half* hbuf; float* xout;
    if constexpr (CIN == 64)       { hbuf = g_h1; xout = g_x1; }
    else if constexpr (CIN == 128) { hbuf = g_h2; xout = g_x2; }
    else                           { hbuf = g_h3; xout = g_x3; }

    int gw = (blockIdx.x * blockDim.x + threadIdx.x) >> 5;
    int L = threadIdx.x & 31;
    if (gw >= N_NODES) return;
    int beg = g_rowptr[gw], end = g_rowptr[gw + 1];
    const __half2 NEGH = __half2half2(__ushort_as_half((unsigned short)0xFC00));

    __half2 m[H2];
#pragma unroll
    for (int k = 0; k < H2; k++) m[k] = NEGH;

    int e = beg;
    for (; e + 2 <= end; e += 2) {
        int s0 = g_esrc[e], s1 = g_esrc[e + 1];
        const __half* p0 = hbuf + (size_t)s0 * CIN + CPL * L;
        const __half* p1 = hbuf + (size_t)s1 * CIN + CPL * L;
        if constexpr (H2 == 1) {
            __half2 v0 = *reinterpret_cast<const __half2*>(p0);
            __half2 v1 = *reinterpret_cast<const __half2*>(p1);
            m[0] = __hmax2(m[0], __hmax2(v0, v1));
        } else if constexpr (H2 == 2) {
            uint2 r0 = *reinterpret_cast<const uint2*>(p0);
            uint2 r1 = *reinterpret_cast<const uint2*>(p1);
            const __half2* a = reinterpret_cast<const __half2*>(&r0);
            const __half2* b = reinterpret_cast<const __half2*>(&r1);
#pragma unroll
            for (int k = 0; k < 2; k++) m[k] = __hmax2(m[k], __hmax2(a[k], b[k]));
        } else {
            uint4 r0 = *reinterpret_cast<const uint4*>(p0);
            uint4 r1 = *reinterpret_cast<const uint4*>(p1);
            const __half2* a = reinterpret_cast<const __half2*>(&r0);
            const __half2* b = reinterpret_cast<const __half2*>(&r1);
#pragma unroll
            for (int k = 0; k < 4; k++) m[k] = __hmax2(m[k], __hmax2(a[k], b[k]));
        }
    }
    if (e < end) {
        int s0 = g_esrc[e];
        const __half* p0 = hbuf + (size_t)s0 * CIN + CPL * L;
        if constexpr (H2 == 1) {
            m[0] = __hmax2(m[0], *reinterpret_cast<const __half2*>(p0));
        } else if constexpr (H2 == 2) {
            uint2 r0 = *reinterpret_cast<const uint2*>(p0);
            const __half2* a = reinterpret_cast<const __half2*>(&r0);
#pragma unroll
            for (int k = 0; k < 2; k++) m[k] = __hmax2(m[k], a[k]);
        } else {
            uint4 r0 = *reinterpret_cast<const uint4*>(p0);
            const __half2* a = reinterpret_cast<const __half2*>(&r0);
#pragma unroll
            for (int k = 0; k < 4; k++) m[k] = __hmax2(m[k], a[k]);
        }
    }

    float* orow = xout + (size_t)gw * (2 * CIN) + CIN + CPL * L;
    bool empty = (beg == end);
    if constexpr (H2 == 1) {
        float2 f = empty ? make_float2(0.f, 0.f) : __half22float2(m[0]);
        *reinterpret_cast<float2*>(orow) = f;
    } else if constexpr (H2 == 2) {
        float2 f0 = empty ? make_float2(0.f, 0.f) : __half22float2(m[0]);
        float2 f1 = empty ? make_float2(0.f, 0.f) : __half22float2(m[1]);
        *reinterpret_cast<float4*>(orow) = make_float4(f0.x, f0.y, f1.x, f1.y);
    } else {
#pragma unroll
        for (int k = 0; k < 4; k += 2) {
            float2 f0 = empty ? make_float2(0.f, 0.f) : __half22float2(m[k]);
            float2 f1 = empty ? make_float2(0.f, 0.f) : __half22float2(m[k + 1]);
            *reinterpret_cast<float4*>(orow + 2 * k) = make_float4(f0.x, f0.y, f1.x, f1.y);
        }
    }
}

// ---------------- cluster max-pool ----------------
__global__ void pool_k() {
    int gw = (blockIdx.x * blockDim.x + threadIdx.x) >> 5;
    int L = threadIdx.x & 31;
    if (gw >= N_CLUST) return;
    int beg = g_crow[gw], end = g_crow[gw + 1];
    const float NEG = __int_as_float(0xff800000);
    float4 m[4];
#pragma unroll
    for (int k = 0; k < 4; k++) m[k] = make_float4(NEG, NEG, NEG, NEG);
    for (int e = beg; e < end; e++) {
        int n = g_cnodes[e];
        const float4* r = reinterpret_cast<const float4*>(g_x3 + (size_t)n * 512 + 16 * L);
#pragma unroll
        for (int k = 0; k < 4; k++) m[k] = fmax4(m[k], r[k]);
    }
    if (beg == end) {
#pragma unroll
        for (int k = 0; k < 4; k++) m[k] = make_float4(0.f, 0.f, 0.f, 0.f);
    }
    float4* o = reinterpret_cast<float4*>(g_pooled + (size_t)gw * 512 + 16 * L);
#pragma unroll
    for (int k = 0; k < 4; k++) o[k] = m[k];
}

// ---------------- column L2 norm + scale ----------------
__global__ void colsum_k() {
    int b = blockIdx.x, c = threadIdx.x;
    int per = (N_CLUST + 63) / 64;
    int r0 = b * per;
    int r1 = r0 + per; if (r1 > N_CLUST) r1 = N_CLUST;
    float s = 0.0f;
    for (int r = r0; r < r1; r++) {
        float v = g_pooled[(size_t)r * 512 + c];
        s = fmaf(v, v, s);
    }
    g_partial[b * 512 + c] = s;
}

__global__ void norm_k() {
    int c = threadIdx.x;
    float s = 0.0f;
    for (int b = 0; b < 64; b++) s += g_partial[b * 512 + c];
    g_norms[c] = sqrtf(s);
}

__global__ void scale_k(float* __restrict__ out) {
    int idx = blockIdx.x * blockDim.x + threadIdx.x;
    if (idx < N_CLUST * 512) out[idx] = g_pooled[idx] / g_norms[idx & 511];
    if (idx < 3) g_task[idx] = 0;   // reset work-stealing counters for next replay
}

// ---------------- launch ----------------
extern "C" void kernel_launch(void* const* d_in, const int* in_sizes, int n_in,
                              void* d_out, int out_size) {
    const float* x = (const float*)d_in[0];
    const int* eidx = (const int*)d_in[1];
    const int* clu = (const int*)d_in[2];
    int base = n_in - 18;
    const float* P[18];
    for (int i = 0; i < 18; i++) P[i] = (const float*)d_in[base + i];
    const int* src = eidx;
    const int* dst = eidx + N_EDGES;
    float* out = (float*)d_out;

    constexpr int NW = 16;
    constexpr int NB0 = 8, NB1 = 8, NB2 = 8;
    const int smem0 = (64 * 128 + NW * NB0 * 64) * 4;    //  65536
    const int smem1 = (128 * 128 + NW * NB1 * 128) * 4;  // 131072
    const int smem2 = (256 * 128 + NW * NB2 * 64) * 4;   // 163840 (chunked staging)
    cudaFuncSetAttribute(mlp_k<64, NW, NB0>,  cudaFuncAttributeMaxDynamicSharedMemorySize, smem0);
    cudaFuncSetAttribute(mlp_k<128, NW, NB1>, cudaFuncAttributeMaxDynamicSharedMemorySize, smem1);
    cudaFuncSetAttribute(mlp2_k<NW, NB2>,     cudaFuncAttributeMaxDynamicSharedMemorySize, smem2);

    // Fork: CSR build (side stream) overlaps mlp0 (NULL stream) — disjoint buffers.
    cudaStream_t s2;
    cudaStreamCreateWithFlags(&s2, cudaStreamNonBlocking);
    cudaEvent_t eFork, eJoin;
    cudaEventCreateWithFlags(&eFork, cudaEventDisableTiming);
    cudaEventCreateWithFlags(&eJoin, cudaEventDisableTiming);

    cudaEventRecord(eFork, 0);
    cudaStreamWaitEvent(s2, eFork, 0);

    zero_counts_k<<<196, 256, 0, s2>>>();
    hist_k<<<3125, 256, 0, s2>>>(dst, clu);
    scan_p1_k<<<NBLK_N + NBLK_C, 256, 0, s2>>>();
    scan_p3_k<<<NBLK_N + NBLK_C, 256, 0, s2>>>();
    fill_k<<<3125, 256, 0, s2>>>(src, dst, clu);
    cudaEventRecord(eJoin, s2);

    mlp_k<64, NW, NB0><<<GRID_SMS, NW * 32, smem0>>>(x, P[0], P[1], P[2], P[3], P[4], P[5]);

    cudaStreamWaitEvent(0, eJoin, 0);

    const int aggBlocks = (N_NODES * 32 + 255) / 256;

    agg_k<64><<<aggBlocks, 256>>>();
    mlp_k<128, NW, NB1><<<GRID_SMS, NW * 32, smem1>>>(x, P[6], P[7], P[8], P[9], P[10], P[11]);
    agg_k<128><<<aggBlocks, 256>>>();
    mlp2_k<NW, NB2><<<GRID_SMS, NW * 32, smem2>>>(P[12], P[13], P[14], P[15], P[16], P[17]);
    agg_k<256><<<aggBlocks, 256>>>();

    pool_k<<<(N_CLUST * 32 + 255) / 256, 256>>>();
    colsum_k<<<64, 512>>>();
    norm_k<<<1, 512>>>();
    scale_k<<<(N_CLUST * 512 + 255) / 256, 256>>>(out);

    cudaEventDestroy(eFork);
    cudaEventDestroy(eJoin);
    cudaStreamDestroy(s2);
}